// round 2
// baseline (speedup 1.0000x reference)
#include <cuda_runtime.h>
#include <math.h>

#define B_DIM 32
#define S_DIM 128
#define E_DIM 512
#define F_DIM 2048
#define LN_EPS 1e-5f

typedef unsigned long long u64;

// 32MB scratch for h = x@W1 + b1   (device global: allocation-guard-safe)
__device__ float g_h[(size_t)B_DIM * S_DIM * F_DIM];

// ---------------- cp.async helpers ----------------
__device__ __forceinline__ void cp_async16(void* smem, const void* gmem) {
    unsigned s = (unsigned)__cvta_generic_to_shared(smem);
    asm volatile("cp.async.cg.shared.global [%0], [%1], 16;\n" :: "r"(s), "l"(gmem));
}
__device__ __forceinline__ void cp_async4(void* smem, const void* gmem) {
    unsigned s = (unsigned)__cvta_generic_to_shared(smem);
    asm volatile("cp.async.ca.shared.global [%0], [%1], 4;\n" :: "r"(s), "l"(gmem));
}
__device__ __forceinline__ void cp_commit() { asm volatile("cp.async.commit_group;\n"); }
__device__ __forceinline__ void cp_wait0() { asm volatile("cp.async.wait_group 0;\n"); }

// ---------------- packed f32x2 helpers ----------------
__device__ __forceinline__ void ffma2(u64& d, u64 a, u64 b) {
    asm("fma.rn.f32x2 %0, %1, %2, %0;" : "+l"(d) : "l"(a), "l"(b));
}
__device__ __forceinline__ u64 pack2(float x) {
    u64 r;
    asm("mov.b64 %0, {%1, %1};" : "=l"(r) : "f"(x));
    return r;
}
__device__ __forceinline__ float2 unpack2(u64 v) {
    float2 f;
    asm("mov.b64 {%0, %1}, %2;" : "=f"(f.x), "=f"(f.y) : "l"(v));
    return f;
}

// ----------------------------------------------------------------------------
// Batched-per-s GEMM:  C[b, s, n0..n0+127] = sum_k A[b, s, k] * W[s, k, n] + bias
//                      (+ res if RES)
// A: [B, S, K]   W: [S, K, N]   C/res: [B, S, N]   bias: [S, N]
// Grid: (N/128, S).  Block: 128 threads.  Microtile: 4 rows(b) x 8 cols(n),
// computed as 4x4 packed f32x2 accumulators via fma.rn.f32x2.
// A smem tile stored TRANSPOSED [kk][row] (row-pad 36 floats -> 144B, 16B
// aligned) so the 4 a-values per thread come from ONE LDS.128.
// ----------------------------------------------------------------------------
template<int K_TOT, int N_TOT, bool A_IS_H, bool C_IS_H, bool RES>
__global__ __launch_bounds__(128, 5)
void ffn_gemm(const float* __restrict__ Ag, const float* __restrict__ W,
              const float* __restrict__ bias, const float* __restrict__ res,
              float* __restrict__ Cg)
{
    constexpr int KT = 32;
    constexpr int NT = 128;
    constexpr int NK = K_TOT / KT;
    constexpr int AP = 36;              // padded row (floats): 144B, 16B-aligned

    const int s   = blockIdx.y;
    const int n0  = blockIdx.x * NT;
    const int tid = threadIdx.x;
    const int ty  = tid >> 4;   // 0..7  -> rows ty*4 .. ty*4+3
    const int tx  = tid & 15;   // 0..15 -> cols tx*8 .. tx*8+7
    const int r0  = ty * 4;
    const int c0  = tx * 8;

    __shared__ float As[2][KT][AP];     // TRANSPOSED: [k][b]
    __shared__ float Bs[2][KT][NT];     // [k][n]

    const float* A = A_IS_H ? (const float*)g_h : Ag;
    float*       C = C_IS_H ? (float*)g_h       : Cg;

    const float* Aptr = A + (size_t)s * K_TOT;                  // + b*S*K + k
    const float* Wptr = W + (size_t)s * K_TOT * N_TOT + n0;     // + k*N + n

    auto load_tile = [&](int kt, int bf) {
        const int k0 = kt * KT;
        // A tile: 32(b) x 32(k), gmem-coalesced over k, stored transposed
        #pragma unroll
        for (int p = 0; p < 8; p++) {
            int i  = p * 128 + tid;
            int bb = i >> 5;            // batch row
            int kk = i & 31;            // k within tile
            cp_async4(&As[bf][kk][bb],
                      Aptr + (size_t)bb * (S_DIM * K_TOT) + k0 + kk);
        }
        // B tile: 32(k) x 128(n), 16B cp.async, coalesced over n
        #pragma unroll
        for (int p = 0; p < 8; p++) {
            int i  = p * 128 + tid;
            int rr = i >> 5;
            int c4 = (i & 31) * 4;
            cp_async16(&Bs[bf][rr][c4], Wptr + (size_t)(k0 + rr) * N_TOT + c4);
        }
    };

    u64 acc[4][4];
    #pragma unroll
    for (int i = 0; i < 4; i++)
        #pragma unroll
        for (int j = 0; j < 4; j++) acc[i][j] = 0ull;

    load_tile(0, 0);
    cp_commit();

    int buf = 0;
    for (int kt = 0; kt < NK; kt++) {
        cp_wait0();
        __syncthreads();                 // tile 'buf' ready; prev compute done
        if (kt + 1 < NK) { load_tile(kt + 1, buf ^ 1); cp_commit(); }

        #pragma unroll
        for (int kk = 0; kk < KT; kk++) {
            // one LDS.128: a-values for this thread's 4 rows
            float4 av = *(const float4*)&As[buf][kk][r0];
            u64 a2[4];
            a2[0] = pack2(av.x); a2[1] = pack2(av.y);
            a2[2] = pack2(av.z); a2[3] = pack2(av.w);
            // two LDS.128: 8 b-values = 4 packed pairs
            ulonglong2 b01 = *(const ulonglong2*)&Bs[buf][kk][c0];
            ulonglong2 b23 = *(const ulonglong2*)&Bs[buf][kk][c0 + 4];
            #pragma unroll
            for (int i = 0; i < 4; i++) {
                ffma2(acc[i][0], a2[i], b01.x);
                ffma2(acc[i][1], a2[i], b01.y);
                ffma2(acc[i][2], a2[i], b23.x);
                ffma2(acc[i][3], a2[i], b23.y);
            }
        }
        buf ^= 1;
    }

    // ---- epilogue: bias (+ residual) ----
    const float* bp = bias + (size_t)s * N_TOT + n0 + c0;
    float bv[8];
    #pragma unroll
    for (int j = 0; j < 8; j++) bv[j] = bp[j];

    #pragma unroll
    for (int i = 0; i < 4; i++) {
        const size_t off = ((size_t)(r0 + i) * S_DIM + s) * N_TOT + n0 + c0;
        float o[8];
        #pragma unroll
        for (int j = 0; j < 4; j++) {
            float2 v = unpack2(acc[i][j]);
            o[2 * j]     = v.x + bv[2 * j];
            o[2 * j + 1] = v.y + bv[2 * j + 1];
        }
        if (RES) {
            const float* rp = res + off;
            #pragma unroll
            for (int j = 0; j < 8; j++) o[j] += rp[j];
        }
        float4* cp4 = (float4*)(C + off);
        cp4[0] = make_float4(o[0], o[1], o[2], o[3]);
        cp4[1] = make_float4(o[4], o[5], o[6], o[7]);
    }
}

// ----------------------------------------------------------------------------
// LayerNorm over last dim (E=512), in-place on d_out. One block per (b,s) row.
// ----------------------------------------------------------------------------
__global__ __launch_bounds__(256)
void ln_kernel(float* __restrict__ y,
               const float* __restrict__ gamma, const float* __restrict__ beta)
{
    const int row = blockIdx.x;                 // b*S + s
    float* p = y + (size_t)row * E_DIM;
    const int t = threadIdx.x;                  // 0..255, 2 elems each

    float2 v = *(const float2*)&p[t * 2];
    float sum = v.x + v.y;
    float sq  = v.x * v.x + v.y * v.y;

    #pragma unroll
    for (int o = 16; o > 0; o >>= 1) {
        sum += __shfl_down_sync(0xffffffffu, sum, o);
        sq  += __shfl_down_sync(0xffffffffu, sq,  o);
    }
    __shared__ float s_sum[8], s_sq[8];
    const int wid = t >> 5, lid = t & 31;
    if (lid == 0) { s_sum[wid] = sum; s_sq[wid] = sq; }
    __syncthreads();

    __shared__ float s_mu, s_inv;
    if (t == 0) {
        float ts = 0.f, tq = 0.f;
        #pragma unroll
        for (int i = 0; i < 8; i++) { ts += s_sum[i]; tq += s_sq[i]; }
        float mu  = ts * (1.0f / E_DIM);
        float var = tq * (1.0f / E_DIM) - mu * mu;
        s_mu  = mu;
        s_inv = rsqrtf(var + LN_EPS);
    }
    __syncthreads();

    const float mu = s_mu, inv = s_inv;
    float2 g = *(const float2*)&gamma[t * 2];
    float2 b = *(const float2*)&beta[t * 2];
    v.x = (v.x - mu) * inv * g.x + b.x;
    v.y = (v.y - mu) * inv * g.y + b.y;
    *(float2*)&p[t * 2] = v;
}

// ----------------------------------------------------------------------------
extern "C" void kernel_launch(void* const* d_in, const int* in_sizes, int n_in,
                              void* d_out, int out_size)
{
    const float* x     = (const float*)d_in[0];
    const float* W1    = (const float*)d_in[1];
    const float* b1    = (const float*)d_in[2];
    const float* W2    = (const float*)d_in[3];
    const float* b2    = (const float*)d_in[4];
    const float* gamma = (const float*)d_in[5];
    const float* beta  = (const float*)d_in[6];
    float* out = (float*)d_out;

    // GEMM1: h = x @ W1 + b1     (K=E=512, N=F=2048) -> g_h
    {
        dim3 grid(F_DIM / 128, S_DIM);
        ffn_gemm<E_DIM, F_DIM, /*A_IS_H=*/false, /*C_IS_H=*/true, /*RES=*/false>
            <<<grid, 128>>>(x, W1, b1, nullptr, nullptr);
    }
    // GEMM2: y = h @ W2 + b2 + x (K=F=2048, N=E=512) -> d_out
    {
        dim3 grid(E_DIM / 128, S_DIM);
        ffn_gemm<F_DIM, E_DIM, /*A_IS_H=*/true, /*C_IS_H=*/false, /*RES=*/true>
            <<<grid, 128>>>(nullptr, W2, b2, x, out);
    }
    // LayerNorm in-place on d_out
    ln_kernel<<<B_DIM * S_DIM, 256>>>(out, gamma, beta);
}

// round 6
// speedup vs baseline: 1.4973x; 1.4973x over previous
#include <cuda_runtime.h>
#include <cuda_bf16.h>
#include <stdint.h>

#define S_DIM 128
#define NB    32          // batch -> MMA N
#define E_DIM 512
#define F_DIM 2048
#define KT    32          // K per stage
#define MT    128         // M tile
#define LN_EPS 1e-5f

// ---------------- scratch (static device mem: allocation-guard-safe) --------
__device__ __align__(16) __nv_bfloat16 g_hh[(size_t)S_DIM * NB * F_DIM];   // h hi [s][b][f]
__device__ __align__(16) __nv_bfloat16 g_hl[(size_t)S_DIM * NB * F_DIM];   // h lo [s][b][f]
__device__ __align__(16) float         g_outt[(size_t)S_DIM * E_DIM * NB]; // y^T [s][e][b]

// ---------------- smem ------------------------------------------------------
union SmemU {
    struct {
        __nv_bfloat16 a_hi[2][KT][136];   // [buf][k][m]  pad 136 (272B rows, ldmatrix conflict-free)
        __nv_bfloat16 a_lo[2][KT][136];
        __nv_bfloat16 b_hi[2][NB][40];    // [buf][n][k]  pad 40 (80B rows, conflict-free)
        __nv_bfloat16 b_lo[2][NB][40];
    } t;                                   // 45056 B
    float c_nm[NB][132];                   // GEMM1 epilogue staging [n][m]
    float c_mn[MT][36];                    // GEMM2 epilogue staging [m][n]
};

// ---------------- helpers ---------------------------------------------------
__device__ __forceinline__ uint32_t sptr(const void* p) {
    return (uint32_t)__cvta_generic_to_shared(p);
}
__device__ __forceinline__ void ldsm_x4(uint32_t* r, uint32_t a) {
    asm volatile("ldmatrix.sync.aligned.m8n8.x4.shared.b16 {%0,%1,%2,%3}, [%4];"
                 : "=r"(r[0]), "=r"(r[1]), "=r"(r[2]), "=r"(r[3]) : "r"(a));
}
__device__ __forceinline__ void ldsm_x4t(uint32_t* r, uint32_t a) {
    asm volatile("ldmatrix.sync.aligned.m8n8.x4.trans.shared.b16 {%0,%1,%2,%3}, [%4];"
                 : "=r"(r[0]), "=r"(r[1]), "=r"(r[2]), "=r"(r[3]) : "r"(a));
}
__device__ __forceinline__ void mma_bf16(float* d, const uint32_t* a, uint32_t b0, uint32_t b1) {
    asm volatile("mma.sync.aligned.m16n8k16.row.col.f32.bf16.bf16.f32 "
                 "{%0,%1,%2,%3}, {%4,%5,%6,%7}, {%8,%9}, {%0,%1,%2,%3};"
                 : "+f"(d[0]), "+f"(d[1]), "+f"(d[2]), "+f"(d[3])
                 : "r"(a[0]), "r"(a[1]), "r"(a[2]), "r"(a[3]), "r"(b0), "r"(b1));
}
// split two fp32 into packed bf16x2 hi + lo
__device__ __forceinline__ void split2(float f0, float f1, uint32_t& hi, uint32_t& lo) {
    __nv_bfloat162 h = __floats2bfloat162_rn(f0, f1);
    float r0 = f0 - __bfloat162float(h.x);
    float r1 = f1 - __bfloat162float(h.y);
    __nv_bfloat162 l = __floats2bfloat162_rn(r0, r1);
    hi = *reinterpret_cast<uint32_t*>(&h);
    lo = *reinterpret_cast<uint32_t*>(&l);
}

// ----------------------------------------------------------------------------
// Warp-MMA batched-per-s GEMM, bf16 hi/lo 3-pass fp32 emulation.
//   D[m, n] = sum_k W[s, k, m0+m] * Bact[n, k]     m-tile 128, n = 32 (batch)
// GEMM1 (B from fp32 x): epilogue -> h hi/lo bf16 [s][b][f]
// GEMM2 (B from h bf16): epilogue -> y^T fp32 [s][e][b] (+bias)
// ----------------------------------------------------------------------------
template<int K_TOT, int M_TOT, bool B_BF16, bool EPI2>
__global__ __launch_bounds__(256, 2)
void ffn_mma(const float* __restrict__ W, const float* __restrict__ Xf,
             const __nv_bfloat16* __restrict__ Bh_g, const __nv_bfloat16* __restrict__ Bl_g,
             const float* __restrict__ bias,
             __nv_bfloat16* __restrict__ Hh, __nv_bfloat16* __restrict__ Hl,
             float* __restrict__ OutT)
{
    constexpr int NC = K_TOT / KT;
    __shared__ SmemU sm;

    const int s    = blockIdx.y;
    const int m0   = blockIdx.x * MT;
    const int tid  = threadIdx.x;
    const int lane = tid & 31;
    const int warp = tid >> 5;

    // ---- staging coords ----
    const int akk = tid >> 3;            // 0..31  k-row
    const int amq = (tid & 7) * 16;      // m offset (16 floats)
    const int bb  = (tid & 127) >> 2;    // 0..31  n-row
    const int bko = (tid & 3) * 8;       // k offset (8 elems)
    const bool bload = tid < 128;

    const float* Abase = W + ((size_t)s * K_TOT + akk) * M_TOT + m0 + amq;

    float4 a4[4];
    float4 bx0, bx1;                     // GEMM1 B staging (fp32)
    uint4  bh4, bl4;                     // GEMM2 B staging (bf16)

    auto LDG = [&](int c) {
        const float* ap = Abase + (size_t)c * KT * M_TOT;
        #pragma unroll
        for (int i = 0; i < 4; i++) a4[i] = *(const float4*)(ap + i * 4);
        if (bload) {
            if (B_BF16) {
                const size_t o = ((size_t)s * NB + bb) * K_TOT + (size_t)c * KT + bko;
                bh4 = *(const uint4*)(Bh_g + o);
                bl4 = *(const uint4*)(Bl_g + o);
            } else {
                const float* xp = Xf + ((size_t)bb * S_DIM + s) * K_TOT + (size_t)c * KT + bko;
                bx0 = *(const float4*)xp;
                bx1 = *(const float4*)(xp + 4);
            }
        }
    };

    auto STS = [&](int buf) {
        uint32_t hi[8], lo[8];
        const float* af = (const float*)a4;
        #pragma unroll
        for (int i = 0; i < 8; i++) split2(af[2 * i], af[2 * i + 1], hi[i], lo[i]);
        uint4* dh = (uint4*)&sm.t.a_hi[buf][akk][amq];
        uint4* dl = (uint4*)&sm.t.a_lo[buf][akk][amq];
        dh[0] = make_uint4(hi[0], hi[1], hi[2], hi[3]);
        dh[1] = make_uint4(hi[4], hi[5], hi[6], hi[7]);
        dl[0] = make_uint4(lo[0], lo[1], lo[2], lo[3]);
        dl[1] = make_uint4(lo[4], lo[5], lo[6], lo[7]);
        if (bload) {
            if (B_BF16) {
                *(uint4*)&sm.t.b_hi[buf][bb][bko] = bh4;
                *(uint4*)&sm.t.b_lo[buf][bb][bko] = bl4;
            } else {
                const float bf[8] = {bx0.x, bx0.y, bx0.z, bx0.w, bx1.x, bx1.y, bx1.z, bx1.w};
                uint32_t h2[4], l2[4];
                #pragma unroll
                for (int j = 0; j < 4; j++) split2(bf[2 * j], bf[2 * j + 1], h2[j], l2[j]);
                *(uint4*)&sm.t.b_hi[buf][bb][bko] = make_uint4(h2[0], h2[1], h2[2], h2[3]);
                *(uint4*)&sm.t.b_lo[buf][bb][bko] = make_uint4(l2[0], l2[1], l2[2], l2[3]);
            }
        }
    };

    // ---- ldmatrix lane addressing ----
    const int a_kr = (lane & 7) + ((lane >> 4) << 3);          // k row within 16-chunk
    const int a_mc = warp * 16 + (((lane >> 3) & 1) << 3);     // m col
    const int b_nr = (lane & 7) + (((lane >> 3) & 1) << 3);    // n row within 16-chunk
    const int b_kc = (lane >> 4) << 3;                         // k col

    float acc[4][4];
    #pragma unroll
    for (int j = 0; j < 4; j++)
        #pragma unroll
        for (int i = 0; i < 4; i++) acc[j][i] = 0.f;

    auto MMA = [&](int buf) {
        #pragma unroll
        for (int kh = 0; kh < 2; kh++) {
            uint32_t ah[4], al[4], bh[8], bl[8];
            ldsm_x4t(ah, sptr(&sm.t.a_hi[buf][kh * 16 + a_kr][a_mc]));
            ldsm_x4t(al, sptr(&sm.t.a_lo[buf][kh * 16 + a_kr][a_mc]));
            #pragma unroll
            for (int q = 0; q < 2; q++) {
                ldsm_x4(bh + 4 * q, sptr(&sm.t.b_hi[buf][q * 16 + b_nr][kh * 16 + b_kc]));
                ldsm_x4(bl + 4 * q, sptr(&sm.t.b_lo[buf][q * 16 + b_nr][kh * 16 + b_kc]));
            }
            #pragma unroll
            for (int j = 0; j < 4; j++) {
                const int q = (j >> 1) * 4 + (j & 1);
                mma_bf16(acc[j], ah, bh[q], bh[q + 2]);
                mma_bf16(acc[j], ah, bl[q], bl[q + 2]);
                mma_bf16(acc[j], al, bh[q], bh[q + 2]);
            }
        }
    };

    // ---- pipeline ----
    LDG(0); STS(0); __syncthreads();
    for (int c = 0; c < NC; c++) {
        const int buf = c & 1;
        if (c + 1 < NC) LDG(c + 1);
        MMA(buf);
        if (c + 1 < NC) { STS(buf ^ 1); __syncthreads(); }
    }
    __syncthreads();   // all MMAs done before smem reuse

    // ---- epilogue ----
    if (!EPI2) {
        // stage C as [n][m]
        #pragma unroll
        for (int j = 0; j < 4; j++) {
            const int n = j * 8 + (lane & 3) * 2;
            const int m = warp * 16 + (lane >> 2);
            sm.c_nm[n][m]         = acc[j][0];
            sm.c_nm[n + 1][m]     = acc[j][1];
            sm.c_nm[n][m + 8]     = acc[j][2];
            sm.c_nm[n + 1][m + 8] = acc[j][3];
        }
        __syncthreads();
        const int n  = tid >> 3;
        const int fo = (tid & 7) * 16;
        const float* bp = bias + (size_t)s * M_TOT + m0 + fo;
        uint32_t hi[8], lo[8];
        #pragma unroll
        for (int q = 0; q < 4; q++) {
            float4 v = *(const float4*)&sm.c_nm[n][fo + q * 4];
            v.x += bp[q * 4]; v.y += bp[q * 4 + 1]; v.z += bp[q * 4 + 2]; v.w += bp[q * 4 + 3];
            split2(v.x, v.y, hi[2 * q], lo[2 * q]);
            split2(v.z, v.w, hi[2 * q + 1], lo[2 * q + 1]);
        }
        const size_t o = ((size_t)s * NB + n) * (size_t)M_TOT + m0 + fo;
        ((uint4*)(Hh + o))[0] = make_uint4(hi[0], hi[1], hi[2], hi[3]);
        ((uint4*)(Hh + o))[1] = make_uint4(hi[4], hi[5], hi[6], hi[7]);
        ((uint4*)(Hl + o))[0] = make_uint4(lo[0], lo[1], lo[2], lo[3]);
        ((uint4*)(Hl + o))[1] = make_uint4(lo[4], lo[5], lo[6], lo[7]);
    } else {
        // stage C as [m][n]
        #pragma unroll
        for (int j = 0; j < 4; j++) {
            const int n = j * 8 + (lane & 3) * 2;
            const int m = warp * 16 + (lane >> 2);
            sm.c_mn[m][n]         = acc[j][0];
            sm.c_mn[m][n + 1]     = acc[j][1];
            sm.c_mn[m + 8][n]     = acc[j][2];
            sm.c_mn[m + 8][n + 1] = acc[j][3];
        }
        __syncthreads();
        const int e  = tid >> 1;
        const int bo = (tid & 1) * 16;
        const float bv = bias[(size_t)s * M_TOT + m0 + e];
        float* dst = OutT + ((size_t)s * M_TOT + m0 + e) * NB + bo;
        #pragma unroll
        for (int q = 0; q < 4; q++) {
            float4 v = *(const float4*)&sm.c_mn[e][bo + q * 4];
            ((float4*)dst)[q] = make_float4(v.x + bv, v.y + bv, v.z + bv, v.w + bv);
        }
    }
}

// ----------------------------------------------------------------------------
// LayerNorm: y = y^T + x (residual), normalize over e, write [b][s][e].
// One block per s. ys smem [E][33] (pad -> conflict-free both access patterns).
// ----------------------------------------------------------------------------
__global__ __launch_bounds__(256)
void ln_kernel(const float* __restrict__ OutT, const float* __restrict__ x,
               const float* __restrict__ gamma, const float* __restrict__ beta,
               float* __restrict__ out)
{
    extern __shared__ float ys[];                 // [E_DIM][33]
    __shared__ float ps[8][NB], pq[8][NB], mu_s[NB], inv_s[NB];
    const int s = blockIdx.x, tid = threadIdx.x, lane = tid & 31, w = tid >> 5;

    // phase 1: x -> ys  (coalesced over e)
    #pragma unroll
    for (int bi = 0; bi < 4; bi++) {
        const int b = w * 4 + bi;
        const float* xp = x + ((size_t)b * S_DIM + s) * E_DIM;
        for (int e = lane; e < E_DIM; e += 32) ys[e * 33 + b] = xp[e];
    }
    __syncthreads();

    // phase 2: add y^T (coalesced over b), accumulate per-b sums
    float sum = 0.f, sq = 0.f;
    const float* op = OutT + (size_t)s * E_DIM * NB;
    for (int e = w; e < E_DIM; e += 8) {
        float v = op[(size_t)e * NB + lane] + ys[e * 33 + lane];
        ys[e * 33 + lane] = v;
        sum += v; sq += v * v;
    }
    ps[w][lane] = sum; pq[w][lane] = sq;
    __syncthreads();

    if (tid < NB) {
        float ts = 0.f, tq = 0.f;
        #pragma unroll
        for (int i = 0; i < 8; i++) { ts += ps[i][tid]; tq += pq[i][tid]; }
        const float mu  = ts * (1.0f / E_DIM);
        const float var = tq * (1.0f / E_DIM) - mu * mu;
        mu_s[tid]  = mu;
        inv_s[tid] = rsqrtf(var + LN_EPS);
    }
    __syncthreads();

    // phase 3: normalize + write (coalesced over e)
    #pragma unroll
    for (int bi = 0; bi < 4; bi++) {
        const int b = w * 4 + bi;
        const float mu = mu_s[b], inv = inv_s[b];
        float* dst = out + ((size_t)b * S_DIM + s) * E_DIM;
        for (int e = lane; e < E_DIM; e += 32)
            dst[e] = (ys[e * 33 + b] - mu) * inv * gamma[e] + beta[e];
    }
}

// ----------------------------------------------------------------------------
extern "C" void kernel_launch(void* const* d_in, const int* in_sizes, int n_in,
                              void* d_out, int out_size)
{
    const float* x     = (const float*)d_in[0];
    const float* W1    = (const float*)d_in[1];
    const float* b1    = (const float*)d_in[2];
    const float* W2    = (const float*)d_in[3];
    const float* b2    = (const float*)d_in[4];
    const float* gamma = (const float*)d_in[5];
    const float* beta  = (const float*)d_in[6];
    float* out = (float*)d_out;

    __nv_bfloat16 *hh, *hl;
    float* outt;
    cudaGetSymbolAddress((void**)&hh,   g_hh);
    cudaGetSymbolAddress((void**)&hl,   g_hl);
    cudaGetSymbolAddress((void**)&outt, g_outt);

    const int ln_smem = E_DIM * 33 * (int)sizeof(float);   // 67584 B
    cudaFuncSetAttribute(ln_kernel, cudaFuncAttributeMaxDynamicSharedMemorySize, ln_smem);

    // GEMM1: h = x @ W1 + b1 -> bf16 hi/lo scratch   (M=F, K=E)
    ffn_mma<E_DIM, F_DIM, false, false><<<dim3(F_DIM / MT, S_DIM), 256>>>(
        W1, x, nullptr, nullptr, b1, hh, hl, nullptr);
    // GEMM2: y^T = h @ W2 + b2 -> fp32 scratch       (M=E, K=F)
    ffn_mma<F_DIM, E_DIM, true, true><<<dim3(E_DIM / MT, S_DIM), 256>>>(
        W2, nullptr, hh, hl, b2, nullptr, nullptr, outt);
    // LN(+residual) -> out [b][s][e]
    ln_kernel<<<S_DIM, 256, ln_smem>>>(outt, x, gamma, beta, out);
}

// round 11
// speedup vs baseline: 1.9219x; 1.2835x over previous
#include <cuda_runtime.h>
#include <cuda_bf16.h>
#include <stdint.h>

#define S_DIM 128
#define NB    32          // batch -> MMA N
#define E_DIM 512
#define F_DIM 2048
#define KT    32          // K per chunk
#define MT    128         // M tile
#define LN_EPS 1e-5f

// ---------------- scratch (static device mem: allocation-guard-safe) --------
__device__ __align__(16) __nv_bfloat16 g_hh[(size_t)S_DIM * NB * F_DIM];   // h hi [s][b][f]
__device__ __align__(16) __nv_bfloat16 g_hl[(size_t)S_DIM * NB * F_DIM];   // h lo [s][b][f]
__device__ __align__(16) float         g_outt[(size_t)S_DIM * E_DIM * NB]; // y^T [s][e][b]

// ---------------- dynamic smem layout (bytes) -------------------------------
// A fp32 stages: 3 x [32][132]f               = 50688
// A bf16 tiles:  2 bufs x (hi[32][136] + lo)  = 34816   (R6-validated layout)
// B stages:      GEMM1 fp32 3 x [32][36]f     = 13824
//                GEMM2 bf16 3 x (hi+lo, 5120) = 15360
// B mma (GEMM1): 2 x 5120                     = 10240
#define A_ST_OFF   0
#define A_ST_SZ    16896
#define ACV_OFF    50688
#define ACV_BUF    17408
#define ACV_LO     8704
#define B_ST_OFF   85504
#define B_F32_SZ   4608
#define B_BF_SZ    5120
#define BMMA_OFF   99328
#define SMEM_BYTES 109568

// ---------------- helpers ---------------------------------------------------
__device__ __forceinline__ uint32_t sptr(const void* p) {
    return (uint32_t)__cvta_generic_to_shared(p);
}
__device__ __forceinline__ void cp_async16(void* smemp, const void* gmem) {
    asm volatile("cp.async.cg.shared.global [%0], [%1], 16;\n"
                 :: "r"(sptr(smemp)), "l"(gmem));
}
__device__ __forceinline__ void cp_commit() { asm volatile("cp.async.commit_group;\n"); }
__device__ __forceinline__ void cp_wait1()  { asm volatile("cp.async.wait_group 1;\n"); }

__device__ __forceinline__ void ldsm_x4(uint32_t* r, uint32_t a) {
    asm volatile("ldmatrix.sync.aligned.m8n8.x4.shared.b16 {%0,%1,%2,%3}, [%4];"
                 : "=r"(r[0]), "=r"(r[1]), "=r"(r[2]), "=r"(r[3]) : "r"(a));
}
__device__ __forceinline__ void ldsm_x4t(uint32_t* r, uint32_t a) {
    asm volatile("ldmatrix.sync.aligned.m8n8.x4.trans.shared.b16 {%0,%1,%2,%3}, [%4];"
                 : "=r"(r[0]), "=r"(r[1]), "=r"(r[2]), "=r"(r[3]) : "r"(a));
}
__device__ __forceinline__ void mma_bf16(float* d, const uint32_t* a, uint32_t b0, uint32_t b1) {
    asm volatile("mma.sync.aligned.m16n8k16.row.col.f32.bf16.bf16.f32 "
                 "{%0,%1,%2,%3}, {%4,%5,%6,%7}, {%8,%9}, {%0,%1,%2,%3};"
                 : "+f"(d[0]), "+f"(d[1]), "+f"(d[2]), "+f"(d[3])
                 : "r"(a[0]), "r"(a[1]), "r"(a[2]), "r"(a[3]), "r"(b0), "r"(b1));
}
// split two fp32 into packed bf16x2 hi + lo
__device__ __forceinline__ void split2(float f0, float f1, uint32_t& hi, uint32_t& lo) {
    __nv_bfloat162 h = __floats2bfloat162_rn(f0, f1);
    float r0 = f0 - __bfloat162float(h.x);
    float r1 = f1 - __bfloat162float(h.y);
    __nv_bfloat162 l = __floats2bfloat162_rn(r0, r1);
    hi = *reinterpret_cast<uint32_t*>(&h);
    lo = *reinterpret_cast<uint32_t*>(&l);
}

// ----------------------------------------------------------------------------
// cp.async-pipelined warp-MMA batched-per-s GEMM, bf16 hi/lo 3-pass fp32 emu.
//   D[m, n] = sum_k W[s, k, m0+m] * Bact[n, k]   (m tile 128, n = 32 batch)
// Per-iteration: wait -> BARRIER (publish cp.async stage: completion is
// per-thread!) -> converts -> BARRIER (publish converts) -> issue -> MMA.
// ----------------------------------------------------------------------------
template<int K_TOT, int M_TOT, bool B_BF16, bool EPI2>
__global__ __launch_bounds__(256, 2)
void ffn_mma(const float* __restrict__ W, const float* __restrict__ Xf,
             const __nv_bfloat16* __restrict__ Bh_g, const __nv_bfloat16* __restrict__ Bl_g,
             const float* __restrict__ bias,
             __nv_bfloat16* __restrict__ Hh, __nv_bfloat16* __restrict__ Hl,
             float* __restrict__ OutT)
{
    constexpr int NC = K_TOT / KT;
    extern __shared__ __align__(16) char smem[];

    const int s    = blockIdx.y;
    const int m0   = blockIdx.x * MT;
    const int tid  = threadIdx.x;
    const int lane = tid & 31;
    const int warp = tid >> 5;

    // ---- stage issue: cp.async chunk c into stage c%3 (one group per call) ----
    auto issue = [&](int c) {
        if (c < NC) {
            const int st = c % 3;
            float* ad = (float*)(smem + A_ST_OFF + st * A_ST_SZ);
            const float* as = W + ((size_t)s * K_TOT + (size_t)c * KT) * M_TOT + m0;
            #pragma unroll
            for (int i = 0; i < 4; i++) {
                const int q = tid + i * 256;
                const int row = q >> 5, col = q & 31;      // 32 rows x 32 x 16B
                cp_async16(ad + row * 132 + col * 4,
                           as + (size_t)row * M_TOT + col * 4);
            }
            if (!B_BF16) {
                // full 32x32-float B tile: 8 x 16B per row, all 256 threads
                const int b = tid >> 3, col = tid & 7;
                float* bd = (float*)(smem + B_ST_OFF + st * B_F32_SZ);
                cp_async16(bd + b * 36 + col * 4,
                           Xf + ((size_t)b * S_DIM + s) * K_TOT + (size_t)c * KT + col * 4);
            } else {
                const int sel = tid >> 7;                   // 0 hi, 1 lo
                const int r = (tid & 127) >> 2, cc = tid & 3;
                const __nv_bfloat16* src = (sel ? Bl_g : Bh_g)
                    + ((size_t)s * NB + r) * K_TOT + (size_t)c * KT + cc * 8;
                char* bd = smem + B_ST_OFF + st * B_BF_SZ + sel * 2560;
                cp_async16(bd + r * 80 + cc * 16, src);
            }
        }
        cp_commit();
    };

    // ---- ldmatrix lane addressing (R6-validated) ----
    const int a_kr = (lane & 7) + ((lane >> 4) << 3);          // k row in 16-chunk
    const int a_mc = warp * 16 + (((lane >> 3) & 1) << 3);     // m col
    const int b_nr = (lane & 7) + (((lane >> 3) & 1) << 3);    // n row in 16-chunk
    const int b_kc = (lane >> 4) << 3;                         // k col

    float acc[4][4];
    #pragma unroll
    for (int j = 0; j < 4; j++)
        #pragma unroll
        for (int i = 0; i < 4; i++) acc[j][i] = 0.f;

    issue(0); issue(1);

    for (int c = 0; c < NC; c++) {
        cp_wait1();                       // this thread's groups <= 1 pending
        __syncthreads();                  // PUBLISH stage c to ALL threads

        // ---- convert A fp32 stage -> bf16 hi/lo tile buf c&1 ----
        {
            const float* apv = (const float*)(smem + A_ST_OFF + (c % 3) * A_ST_SZ)
                               + lane * 132 + warp * 16;
            char* dh = smem + ACV_OFF + (c & 1) * ACV_BUF + lane * 272 + warp * 32;
            float4 v0 = ((const float4*)apv)[0];
            float4 v1 = ((const float4*)apv)[1];
            float4 v2 = ((const float4*)apv)[2];
            float4 v3 = ((const float4*)apv)[3];
            uint32_t h[8], l[8];
            split2(v0.x, v0.y, h[0], l[0]); split2(v0.z, v0.w, h[1], l[1]);
            split2(v1.x, v1.y, h[2], l[2]); split2(v1.z, v1.w, h[3], l[3]);
            split2(v2.x, v2.y, h[4], l[4]); split2(v2.z, v2.w, h[5], l[5]);
            split2(v3.x, v3.y, h[6], l[6]); split2(v3.z, v3.w, h[7], l[7]);
            ((uint4*)dh)[0] = make_uint4(h[0], h[1], h[2], h[3]);
            ((uint4*)dh)[1] = make_uint4(h[4], h[5], h[6], h[7]);
            ((uint4*)(dh + ACV_LO))[0] = make_uint4(l[0], l[1], l[2], l[3]);
            ((uint4*)(dh + ACV_LO))[1] = make_uint4(l[4], l[5], l[6], l[7]);
        }
        if (!B_BF16) {
            // convert B fp32 stage -> bf16 hi/lo double buffer (128 threads)
            if (tid < 128) {
                const int bb = tid >> 2, bko = (tid & 3) * 8;
                const float* bs = (const float*)(smem + B_ST_OFF + (c % 3) * B_F32_SZ)
                                  + bb * 36 + bko;
                float4 v0 = *(const float4*)bs;
                float4 v1 = *(const float4*)(bs + 4);
                uint32_t h2[4], l2[4];
                split2(v0.x, v0.y, h2[0], l2[0]);
                split2(v0.z, v0.w, h2[1], l2[1]);
                split2(v1.x, v1.y, h2[2], l2[2]);
                split2(v1.z, v1.w, h2[3], l2[3]);
                char* dh = smem + BMMA_OFF + (c & 1) * 5120 + bb * 80 + bko * 2;
                *(uint4*)dh          = make_uint4(h2[0], h2[1], h2[2], h2[3]);
                *(uint4*)(dh + 2560) = make_uint4(l2[0], l2[1], l2[2], l2[3]);
            }
        }
        __syncthreads();                  // publish converts; fences MMA(c-1)
        issue(c + 2);

        // ---- MMA on chunk c (R6-validated ldsm path) ----
        const char* ahb = smem + ACV_OFF + (c & 1) * ACV_BUF;
        const char* bbp = B_BF16 ? smem + B_ST_OFF + (c % 3) * B_BF_SZ
                                 : smem + BMMA_OFF + (c & 1) * 5120;
        #pragma unroll
        for (int kh = 0; kh < 2; kh++) {
            uint32_t ah[4], al[4], bh[8], bl[8];
            const uint32_t aro = (uint32_t)((kh * 16 + a_kr) * 272 + a_mc * 2);
            ldsm_x4t(ah, sptr(ahb) + aro);
            ldsm_x4t(al, sptr(ahb) + ACV_LO + aro);
            #pragma unroll
            for (int q = 0; q < 2; q++) {
                const uint32_t ro = (uint32_t)((q * 16 + b_nr) * 80 + (kh * 16 + b_kc) * 2);
                ldsm_x4(bh + 4 * q, sptr(bbp) + ro);
                ldsm_x4(bl + 4 * q, sptr(bbp) + 2560 + ro);
            }
            #pragma unroll
            for (int j = 0; j < 4; j++) {
                const int q = (j >> 1) * 4 + (j & 1);
                mma_bf16(acc[j], ah, bh[q], bh[q + 2]);
                mma_bf16(acc[j], ah, bl[q], bl[q + 2]);
                mma_bf16(acc[j], al, bh[q], bh[q + 2]);
            }
        }
    }
    __syncthreads();                      // all MMAs done before smem reuse

    // ---- epilogue (R6-validated) ----
    if (!EPI2) {
        float (*c_nm)[132] = (float(*)[132])smem;
        #pragma unroll
        for (int j = 0; j < 4; j++) {
            const int n = j * 8 + (lane & 3) * 2;
            const int m = warp * 16 + (lane >> 2);
            c_nm[n][m]         = acc[j][0];
            c_nm[n + 1][m]     = acc[j][1];
            c_nm[n][m + 8]     = acc[j][2];
            c_nm[n + 1][m + 8] = acc[j][3];
        }
        __syncthreads();
        const int n  = tid >> 3;
        const int fo = (tid & 7) * 16;
        const float* bp = bias + (size_t)s * M_TOT + m0 + fo;
        uint32_t hi[8], lo[8];
        #pragma unroll
        for (int q = 0; q < 4; q++) {
            float4 v = *(const float4*)&c_nm[n][fo + q * 4];
            v.x += bp[q * 4]; v.y += bp[q * 4 + 1]; v.z += bp[q * 4 + 2]; v.w += bp[q * 4 + 3];
            split2(v.x, v.y, hi[2 * q], lo[2 * q]);
            split2(v.z, v.w, hi[2 * q + 1], lo[2 * q + 1]);
        }
        const size_t o = ((size_t)s * NB + n) * (size_t)M_TOT + m0 + fo;
        ((uint4*)(Hh + o))[0] = make_uint4(hi[0], hi[1], hi[2], hi[3]);
        ((uint4*)(Hh + o))[1] = make_uint4(hi[4], hi[5], hi[6], hi[7]);
        ((uint4*)(Hl + o))[0] = make_uint4(lo[0], lo[1], lo[2], lo[3]);
        ((uint4*)(Hl + o))[1] = make_uint4(lo[4], lo[5], lo[6], lo[7]);
    } else {
        float (*c_mn)[36] = (float(*)[36])smem;
        #pragma unroll
        for (int j = 0; j < 4; j++) {
            const int n = j * 8 + (lane & 3) * 2;
            const int m = warp * 16 + (lane >> 2);
            c_mn[m][n]         = acc[j][0];
            c_mn[m][n + 1]     = acc[j][1];
            c_mn[m + 8][n]     = acc[j][2];
            c_mn[m + 8][n + 1] = acc[j][3];
        }
        __syncthreads();
        const int e  = tid >> 1;
        const int bo = (tid & 1) * 16;
        const float bv = bias[(size_t)s * M_TOT + m0 + e];
        float* dst = OutT + ((size_t)s * M_TOT + m0 + e) * NB + bo;
        #pragma unroll
        for (int q = 0; q < 4; q++) {
            float4 v = *(const float4*)&c_mn[e][bo + q * 4];
            ((float4*)dst)[q] = make_float4(v.x + bv, v.y + bv, v.z + bv, v.w + bv);
        }
    }
}

// ----------------------------------------------------------------------------
// LayerNorm: y = y^T + x (residual), normalize over e, write [b][s][e].
// ----------------------------------------------------------------------------
__global__ __launch_bounds__(256)
void ln_kernel(const float* __restrict__ OutT, const float* __restrict__ x,
               const float* __restrict__ gamma, const float* __restrict__ beta,
               float* __restrict__ out)
{
    extern __shared__ float ys[];                 // [E_DIM][33]
    __shared__ float ps[8][NB], pq[8][NB], mu_s[NB], inv_s[NB];
    const int s = blockIdx.x, tid = threadIdx.x, lane = tid & 31, w = tid >> 5;

    #pragma unroll
    for (int bi = 0; bi < 4; bi++) {
        const int b = w * 4 + bi;
        const float* xp = x + ((size_t)b * S_DIM + s) * E_DIM;
        for (int e = lane; e < E_DIM; e += 32) ys[e * 33 + b] = xp[e];
    }
    __syncthreads();

    float sum = 0.f, sq = 0.f;
    const float* op = OutT + (size_t)s * E_DIM * NB;
    for (int e = w; e < E_DIM; e += 8) {
        float v = op[(size_t)e * NB + lane] + ys[e * 33 + lane];
        ys[e * 33 + lane] = v;
        sum += v; sq += v * v;
    }
    ps[w][lane] = sum; pq[w][lane] = sq;
    __syncthreads();

    if (tid < NB) {
        float ts = 0.f, tq = 0.f;
        #pragma unroll
        for (int i = 0; i < 8; i++) { ts += ps[i][tid]; tq += pq[i][tid]; }
        const float mu  = ts * (1.0f / E_DIM);
        const float var = tq * (1.0f / E_DIM) - mu * mu;
        mu_s[tid]  = mu;
        inv_s[tid] = rsqrtf(var + LN_EPS);
    }
    __syncthreads();

    #pragma unroll
    for (int bi = 0; bi < 4; bi++) {
        const int b = w * 4 + bi;
        const float mu = mu_s[b], inv = inv_s[b];
        float* dst = out + ((size_t)b * S_DIM + s) * E_DIM;
        for (int e = lane; e < E_DIM; e += 32)
            dst[e] = (ys[e * 33 + b] - mu) * inv * gamma[e] + beta[e];
    }
}

// ----------------------------------------------------------------------------
extern "C" void kernel_launch(void* const* d_in, const int* in_sizes, int n_in,
                              void* d_out, int out_size)
{
    const float* x     = (const float*)d_in[0];
    const float* W1    = (const float*)d_in[1];
    const float* b1    = (const float*)d_in[2];
    const float* W2    = (const float*)d_in[3];
    const float* b2    = (const float*)d_in[4];
    const float* gamma = (const float*)d_in[5];
    const float* beta  = (const float*)d_in[6];
    float* out = (float*)d_out;

    __nv_bfloat16 *hh, *hl;
    float* outt;
    cudaGetSymbolAddress((void**)&hh,   g_hh);
    cudaGetSymbolAddress((void**)&hl,   g_hl);
    cudaGetSymbolAddress((void**)&outt, g_outt);

    const int ln_smem = E_DIM * 33 * (int)sizeof(float);   // 67584 B
    cudaFuncSetAttribute(ln_kernel, cudaFuncAttributeMaxDynamicSharedMemorySize, ln_smem);
    cudaFuncSetAttribute(ffn_mma<E_DIM, F_DIM, false, false>,
                         cudaFuncAttributeMaxDynamicSharedMemorySize, SMEM_BYTES);
    cudaFuncSetAttribute(ffn_mma<F_DIM, E_DIM, true, true>,
                         cudaFuncAttributeMaxDynamicSharedMemorySize, SMEM_BYTES);

    // GEMM1: h = x @ W1 + b1 -> bf16 hi/lo scratch   (M=F, K=E)
    ffn_mma<E_DIM, F_DIM, false, false><<<dim3(F_DIM / MT, S_DIM), 256, SMEM_BYTES>>>(
        W1, x, nullptr, nullptr, b1, hh, hl, nullptr);
    // GEMM2: y^T = h @ W2 + b2 -> fp32 scratch       (M=E, K=F)
    ffn_mma<F_DIM, E_DIM, true, true><<<dim3(E_DIM / MT, S_DIM), 256, SMEM_BYTES>>>(
        W2, nullptr, hh, hl, b2, nullptr, nullptr, outt);
    // LN(+residual) -> out [b][s][e]
    ln_kernel<<<S_DIM, 256, ln_smem>>>(outt, x, gamma, beta, out);
}

// round 12
// speedup vs baseline: 1.9225x; 1.0003x over previous
#include <cuda_runtime.h>
#include <cuda_bf16.h>
#include <stdint.h>

#define S_DIM 128
#define NB    32          // batch -> MMA N
#define E_DIM 512
#define F_DIM 2048
#define KT    32          // K per chunk
#define MT    128         // M tile
#define LN_EPS 1e-5f

// ---------------- scratch (static device mem: allocation-guard-safe) --------
__device__ __align__(16) __nv_bfloat16 g_hh[(size_t)S_DIM * NB * F_DIM];   // h hi [s][b][f]
__device__ __align__(16) __nv_bfloat16 g_hl[(size_t)S_DIM * NB * F_DIM];   // h lo [s][b][f]
__device__ __align__(16) float         g_outt[(size_t)S_DIM * E_DIM * NB]; // y^T [s][e][b]

// ---------------- dynamic smem layout (bytes) -------------------------------
// A fp32 stages: 3 x [32][132]f               = 50688
// A bf16 tiles:  2 bufs x (hi[32][136] + lo)  = 34816   (R6-validated layout)
// B stages:      GEMM1 fp32 3 x [32][36]f     = 13824
//                GEMM2 bf16 3 x (hi+lo, 5120) = 15360
// B mma (GEMM1): 2 x 5120                     = 10240
#define A_ST_OFF   0
#define A_ST_SZ    16896
#define ACV_OFF    50688
#define ACV_BUF    17408
#define ACV_LO     8704
#define B_ST_OFF   85504
#define B_F32_SZ   4608
#define B_BF_SZ    5120
#define BMMA_OFF   99328
#define SMEM_BYTES 109568

// ---------------- helpers ---------------------------------------------------
__device__ __forceinline__ uint32_t sptr(const void* p) {
    return (uint32_t)__cvta_generic_to_shared(p);
}
__device__ __forceinline__ void cp_async16(void* smemp, const void* gmem) {
    asm volatile("cp.async.cg.shared.global [%0], [%1], 16;\n"
                 :: "r"(sptr(smemp)), "l"(gmem));
}
__device__ __forceinline__ void cp_commit() { asm volatile("cp.async.commit_group;\n"); }
__device__ __forceinline__ void cp_wait1()  { asm volatile("cp.async.wait_group 1;\n"); }

__device__ __forceinline__ void ldsm_x4(uint32_t* r, uint32_t a) {
    asm volatile("ldmatrix.sync.aligned.m8n8.x4.shared.b16 {%0,%1,%2,%3}, [%4];"
                 : "=r"(r[0]), "=r"(r[1]), "=r"(r[2]), "=r"(r[3]) : "r"(a));
}
__device__ __forceinline__ void ldsm_x4t(uint32_t* r, uint32_t a) {
    asm volatile("ldmatrix.sync.aligned.m8n8.x4.trans.shared.b16 {%0,%1,%2,%3}, [%4];"
                 : "=r"(r[0]), "=r"(r[1]), "=r"(r[2]), "=r"(r[3]) : "r"(a));
}
__device__ __forceinline__ void mma_bf16(float* d, const uint32_t* a, uint32_t b0, uint32_t b1) {
    asm volatile("mma.sync.aligned.m16n8k16.row.col.f32.bf16.bf16.f32 "
                 "{%0,%1,%2,%3}, {%4,%5,%6,%7}, {%8,%9}, {%0,%1,%2,%3};"
                 : "+f"(d[0]), "+f"(d[1]), "+f"(d[2]), "+f"(d[3])
                 : "r"(a[0]), "r"(a[1]), "r"(a[2]), "r"(a[3]), "r"(b0), "r"(b1));
}
// split two fp32 into packed bf16x2 hi + lo
__device__ __forceinline__ void split2(float f0, float f1, uint32_t& hi, uint32_t& lo) {
    __nv_bfloat162 h = __floats2bfloat162_rn(f0, f1);
    float r0 = f0 - __bfloat162float(h.x);
    float r1 = f1 - __bfloat162float(h.y);
    __nv_bfloat162 l = __floats2bfloat162_rn(r0, r1);
    hi = *reinterpret_cast<uint32_t*>(&h);
    lo = *reinterpret_cast<uint32_t*>(&l);
}

// ----------------------------------------------------------------------------
// cp.async-pipelined warp-MMA batched-per-s GEMM, bf16 hi/lo 3-pass fp32 emu.
//   D[m, n] = sum_k W[s, k, m0+m] * Bact[n, k]   (m tile 128, n = 32 batch)
// OWNER-CONVERT pipeline, ONE barrier per chunk:
//   wait1 -> convert(c) [each thread splits its OWN cp.async'd floats]
//   -> bar (publish conv bufs + stage c) -> issue(c+2) -> MMA(c)
// MMA(c) and convert(c+1) share an inter-barrier interval -> tensor overlap.
// ----------------------------------------------------------------------------
template<int K_TOT, int M_TOT, bool B_BF16, bool EPI2>
__global__ __launch_bounds__(256, 2)
void ffn_mma(const float* __restrict__ W, const float* __restrict__ Xf,
             const __nv_bfloat16* __restrict__ Bh_g, const __nv_bfloat16* __restrict__ Bl_g,
             const float* __restrict__ bias,
             __nv_bfloat16* __restrict__ Hh, __nv_bfloat16* __restrict__ Hl,
             float* __restrict__ OutT)
{
    constexpr int NC = K_TOT / KT;
    extern __shared__ __align__(16) char smem[];

    const int s    = blockIdx.y;
    const int m0   = blockIdx.x * MT;
    const int tid  = threadIdx.x;
    const int lane = tid & 31;
    const int warp = tid >> 5;

    // ---- stage issue: cp.async chunk c into stage c%3 (one group per call) ----
    auto issue = [&](int c) {
        if (c < NC) {
            const int st = c % 3;
            float* ad = (float*)(smem + A_ST_OFF + st * A_ST_SZ);
            const float* as = W + ((size_t)s * K_TOT + (size_t)c * KT) * M_TOT + m0;
            #pragma unroll
            for (int i = 0; i < 4; i++) {
                const int q = tid + i * 256;
                const int row = q >> 5, col = q & 31;      // 32 rows x 32 x 16B
                cp_async16(ad + row * 132 + col * 4,
                           as + (size_t)row * M_TOT + col * 4);
            }
            if (!B_BF16) {
                // full 32x32-float B tile: 8 x 16B per row, all 256 threads
                const int b = tid >> 3, col = tid & 7;
                float* bd = (float*)(smem + B_ST_OFF + st * B_F32_SZ);
                cp_async16(bd + b * 36 + col * 4,
                           Xf + ((size_t)b * S_DIM + s) * K_TOT + (size_t)c * KT + col * 4);
            } else {
                const int sel = tid >> 7;                   // 0 hi, 1 lo
                const int r = (tid & 127) >> 2, cc = tid & 3;
                const __nv_bfloat16* src = (sel ? Bl_g : Bh_g)
                    + ((size_t)s * NB + r) * K_TOT + (size_t)c * KT + cc * 8;
                char* bd = smem + B_ST_OFF + st * B_BF_SZ + sel * 2560;
                cp_async16(bd + r * 80 + cc * 16, src);
            }
        }
        cp_commit();
    };

    // ---- ldmatrix lane addressing (R6-validated) ----
    const int a_kr = (lane & 7) + ((lane >> 4) << 3);          // k row in 16-chunk
    const int a_mc = warp * 16 + (((lane >> 3) & 1) << 3);     // m col
    const int b_nr = (lane & 7) + (((lane >> 3) & 1) << 3);    // n row in 16-chunk
    const int b_kc = (lane >> 4) << 3;                         // k col

    float acc[4][4];
    #pragma unroll
    for (int j = 0; j < 4; j++)
        #pragma unroll
        for (int i = 0; i < 4; i++) acc[j][i] = 0.f;

    issue(0); issue(1);

    for (int c = 0; c < NC; c++) {
        cp_wait1();                       // this thread's group <= c complete

        // ---- OWNER-convert A: the 16 floats this thread cp.async'd ----
        // issue mapping: thread wrote rows (tid>>5)+8i, float cols (tid&31)*4
        {
            const float* ast = (const float*)(smem + A_ST_OFF + (c % 3) * A_ST_SZ);
            char* dh = smem + ACV_OFF + (c & 1) * ACV_BUF;
            const int r0 = tid >> 5;
            const int cc = tid & 31;
            #pragma unroll
            for (int i = 0; i < 4; i++) {
                const int r = r0 + i * 8;
                float4 v = *(const float4*)(ast + r * 132 + cc * 4);
                uint32_t h0, l0, h1, l1;
                split2(v.x, v.y, h0, l0);
                split2(v.z, v.w, h1, l1);
                *(uint2*)(dh + r * 272 + cc * 8)          = make_uint2(h0, h1);
                *(uint2*)(dh + ACV_LO + r * 272 + cc * 8) = make_uint2(l0, l1);
            }
        }
        if (!B_BF16) {
            // OWNER-convert B: thread wrote row tid>>3, float cols (tid&7)*4
            const int b = tid >> 3, cc = tid & 7;
            const float* bs = (const float*)(smem + B_ST_OFF + (c % 3) * B_F32_SZ)
                              + b * 36 + cc * 4;
            float4 v = *(const float4*)bs;
            uint32_t h0, l0, h1, l1;
            split2(v.x, v.y, h0, l0);
            split2(v.z, v.w, h1, l1);
            char* dh = smem + BMMA_OFF + (c & 1) * 5120 + b * 80 + cc * 8;
            *(uint2*)dh          = make_uint2(h0, h1);
            *(uint2*)(dh + 2560) = make_uint2(l0, l1);
        }
        __syncthreads();                  // publish converts + stage c; fence MMA(c-1)
        issue(c + 2);

        // ---- MMA on chunk c (R6-validated ldsm path) ----
        const char* ahb = smem + ACV_OFF + (c & 1) * ACV_BUF;
        const char* bbp = B_BF16 ? smem + B_ST_OFF + (c % 3) * B_BF_SZ
                                 : smem + BMMA_OFF + (c & 1) * 5120;
        #pragma unroll
        for (int kh = 0; kh < 2; kh++) {
            uint32_t ah[4], al[4], bh[8], bl[8];
            const uint32_t aro = (uint32_t)((kh * 16 + a_kr) * 272 + a_mc * 2);
            ldsm_x4t(ah, sptr(ahb) + aro);
            ldsm_x4t(al, sptr(ahb) + ACV_LO + aro);
            #pragma unroll
            for (int q = 0; q < 2; q++) {
                const uint32_t ro = (uint32_t)((q * 16 + b_nr) * 80 + (kh * 16 + b_kc) * 2);
                ldsm_x4(bh + 4 * q, sptr(bbp) + ro);
                ldsm_x4(bl + 4 * q, sptr(bbp) + 2560 + ro);
            }
            #pragma unroll
            for (int j = 0; j < 4; j++) {
                const int q = (j >> 1) * 4 + (j & 1);
                mma_bf16(acc[j], ah, bh[q], bh[q + 2]);
                mma_bf16(acc[j], ah, bl[q], bl[q + 2]);
                mma_bf16(acc[j], al, bh[q], bh[q + 2]);
            }
        }
    }
    __syncthreads();                      // all MMAs done before smem reuse

    // ---- epilogue (R6-validated) ----
    if (!EPI2) {
        float (*c_nm)[132] = (float(*)[132])smem;
        #pragma unroll
        for (int j = 0; j < 4; j++) {
            const int n = j * 8 + (lane & 3) * 2;
            const int m = warp * 16 + (lane >> 2);
            c_nm[n][m]         = acc[j][0];
            c_nm[n + 1][m]     = acc[j][1];
            c_nm[n][m + 8]     = acc[j][2];
            c_nm[n + 1][m + 8] = acc[j][3];
        }
        __syncthreads();
        const int n  = tid >> 3;
        const int fo = (tid & 7) * 16;
        const float* bp = bias + (size_t)s * M_TOT + m0 + fo;
        uint32_t hi[8], lo[8];
        #pragma unroll
        for (int q = 0; q < 4; q++) {
            float4 v = *(const float4*)&c_nm[n][fo + q * 4];
            v.x += bp[q * 4]; v.y += bp[q * 4 + 1]; v.z += bp[q * 4 + 2]; v.w += bp[q * 4 + 3];
            split2(v.x, v.y, hi[2 * q], lo[2 * q]);
            split2(v.z, v.w, hi[2 * q + 1], lo[2 * q + 1]);
        }
        const size_t o = ((size_t)s * NB + n) * (size_t)M_TOT + m0 + fo;
        ((uint4*)(Hh + o))[0] = make_uint4(hi[0], hi[1], hi[2], hi[3]);
        ((uint4*)(Hh + o))[1] = make_uint4(hi[4], hi[5], hi[6], hi[7]);
        ((uint4*)(Hl + o))[0] = make_uint4(lo[0], lo[1], lo[2], lo[3]);
        ((uint4*)(Hl + o))[1] = make_uint4(lo[4], lo[5], lo[6], lo[7]);
    } else {
        float (*c_mn)[36] = (float(*)[36])smem;
        #pragma unroll
        for (int j = 0; j < 4; j++) {
            const int n = j * 8 + (lane & 3) * 2;
            const int m = warp * 16 + (lane >> 2);
            c_mn[m][n]         = acc[j][0];
            c_mn[m][n + 1]     = acc[j][1];
            c_mn[m + 8][n]     = acc[j][2];
            c_mn[m + 8][n + 1] = acc[j][3];
        }
        __syncthreads();
        const int e  = tid >> 1;
        const int bo = (tid & 1) * 16;
        const float bv = bias[(size_t)s * M_TOT + m0 + e];
        float* dst = OutT + ((size_t)s * M_TOT + m0 + e) * NB + bo;
        #pragma unroll
        for (int q = 0; q < 4; q++) {
            float4 v = *(const float4*)&c_mn[e][bo + q * 4];
            ((float4*)dst)[q] = make_float4(v.x + bv, v.y + bv, v.z + bv, v.w + bv);
        }
    }
}

// ----------------------------------------------------------------------------
// LayerNorm: y = y^T + x (residual), normalize over e, write [b][s][e].
// ----------------------------------------------------------------------------
__global__ __launch_bounds__(256)
void ln_kernel(const float* __restrict__ OutT, const float* __restrict__ x,
               const float* __restrict__ gamma, const float* __restrict__ beta,
               float* __restrict__ out)
{
    extern __shared__ float ys[];                 // [E_DIM][33]
    __shared__ float ps[8][NB], pq[8][NB], mu_s[NB], inv_s[NB];
    const int s = blockIdx.x, tid = threadIdx.x, lane = tid & 31, w = tid >> 5;

    #pragma unroll
    for (int bi = 0; bi < 4; bi++) {
        const int b = w * 4 + bi;
        const float* xp = x + ((size_t)b * S_DIM + s) * E_DIM;
        for (int e = lane; e < E_DIM; e += 32) ys[e * 33 + b] = xp[e];
    }
    __syncthreads();

    float sum = 0.f, sq = 0.f;
    const float* op = OutT + (size_t)s * E_DIM * NB;
    for (int e = w; e < E_DIM; e += 8) {
        float v = op[(size_t)e * NB + lane] + ys[e * 33 + lane];
        ys[e * 33 + lane] = v;
        sum += v; sq += v * v;
    }
    ps[w][lane] = sum; pq[w][lane] = sq;
    __syncthreads();

    if (tid < NB) {
        float ts = 0.f, tq = 0.f;
        #pragma unroll
        for (int i = 0; i < 8; i++) { ts += ps[i][tid]; tq += pq[i][tid]; }
        const float mu  = ts * (1.0f / E_DIM);
        const float var = tq * (1.0f / E_DIM) - mu * mu;
        mu_s[tid]  = mu;
        inv_s[tid] = rsqrtf(var + LN_EPS);
    }
    __syncthreads();

    #pragma unroll
    for (int bi = 0; bi < 4; bi++) {
        const int b = w * 4 + bi;
        const float mu = mu_s[b], inv = inv_s[b];
        float* dst = out + ((size_t)b * S_DIM + s) * E_DIM;
        for (int e = lane; e < E_DIM; e += 32)
            dst[e] = (ys[e * 33 + b] - mu) * inv * gamma[e] + beta[e];
    }
}

// ----------------------------------------------------------------------------
extern "C" void kernel_launch(void* const* d_in, const int* in_sizes, int n_in,
                              void* d_out, int out_size)
{
    const float* x     = (const float*)d_in[0];
    const float* W1    = (const float*)d_in[1];
    const float* b1    = (const float*)d_in[2];
    const float* W2    = (const float*)d_in[3];
    const float* b2    = (const float*)d_in[4];
    const float* gamma = (const float*)d_in[5];
    const float* beta  = (const float*)d_in[6];
    float* out = (float*)d_out;

    __nv_bfloat16 *hh, *hl;
    float* outt;
    cudaGetSymbolAddress((void**)&hh,   g_hh);
    cudaGetSymbolAddress((void**)&hl,   g_hl);
    cudaGetSymbolAddress((void**)&outt, g_outt);

    const int ln_smem = E_DIM * 33 * (int)sizeof(float);   // 67584 B
    cudaFuncSetAttribute(ln_kernel, cudaFuncAttributeMaxDynamicSharedMemorySize, ln_smem);
    cudaFuncSetAttribute(ffn_mma<E_DIM, F_DIM, false, false>,
                         cudaFuncAttributeMaxDynamicSharedMemorySize, SMEM_BYTES);
    cudaFuncSetAttribute(ffn_mma<F_DIM, E_DIM, true, true>,
                         cudaFuncAttributeMaxDynamicSharedMemorySize, SMEM_BYTES);

    // GEMM1: h = x @ W1 + b1 -> bf16 hi/lo scratch   (M=F, K=E)
    ffn_mma<E_DIM, F_DIM, false, false><<<dim3(F_DIM / MT, S_DIM), 256, SMEM_BYTES>>>(
        W1, x, nullptr, nullptr, b1, hh, hl, nullptr);
    // GEMM2: y^T = h @ W2 + b2 -> fp32 scratch       (M=E, K=F)
    ffn_mma<F_DIM, E_DIM, true, true><<<dim3(E_DIM / MT, S_DIM), 256, SMEM_BYTES>>>(
        W2, nullptr, hh, hl, b2, nullptr, nullptr, outt);
    // LN(+residual) -> out [b][s][e]
    ln_kernel<<<S_DIM, 256, ln_smem>>>(outt, x, gamma, beta, out);
}